// round 4
// baseline (speedup 1.0000x reference)
#include <cuda_runtime.h>
#include <cstdint>

#define B_DIM 1024
#define T_DIM 200
#define E_DIM 128
#define H_DIM 64
#define T_TILE 256   // covers T=200, padded with zeros

// smem layout (floats):
//   ks   [E_DIM][T_TILE]   = 32768
//   weff [E_DIM][H_DIM]    =  8192
//   qs   [E_DIM]           =   128
//   cs   [H_DIM]           =    64
//   w1s  [H_DIM]           =    64
#define SMEM_FLOATS (E_DIM * T_TILE + E_DIM * H_DIM + E_DIM + H_DIM + H_DIM)
#define SMEM_BYTES  (SMEM_FLOATS * 4)

// packed f32x2 FMA: acc = a*b + acc (elementwise on both halves)
#define FMA2(accv, av, bv) \
    asm("fma.rn.f32x2 %0, %1, %2, %0;" : "+l"(accv) : "l"(av), "l"(bv))

__global__ void __launch_bounds__(256, 1)
lau_kernel(const float* __restrict__ query,   // [B,1,E]
           const float* __restrict__ keys,    // [B,T,E]
           const float* __restrict__ W0,      // [4E,H]
           const float* __restrict__ b0,      // [H]
           const float* __restrict__ W1,      // [H,1]
           const float* __restrict__ b1,      // [1]
           float* __restrict__ out)           // [B,T,1]
{
    extern __shared__ float smem[];
    float* ks   = smem;
    float* weff = smem + E_DIM * T_TILE;
    float* qs   = weff + E_DIM * H_DIM;
    float* cs   = qs + E_DIM;
    float* w1s  = cs + H_DIM;

    const int b   = blockIdx.x;
    const int tid = threadIdx.x;

    // ---- stage q and W1 ----
    if (tid < E_DIM) qs[tid] = query[b * E_DIM + tid];
    if (tid >= E_DIM && tid < E_DIM + H_DIM) w1s[tid - E_DIM] = W1[tid - E_DIM];
    __syncthreads();

    // ---- build Weff[e][h] = W0k - W0d + q[e]*W0m  (vectorized float4) ----
    {
        const float4* W0k = (const float4*)(W0 + 128 * H_DIM);
        const float4* W0d = (const float4*)(W0 + 256 * H_DIM);
        const float4* W0m = (const float4*)(W0 + 384 * H_DIM);
        float4* wf = (float4*)weff;
        const int NV = E_DIM * H_DIM / 4;  // 2048
        #pragma unroll 4
        for (int i = tid; i < NV; i += 256) {
            int e = i >> 4;                // H/4 = 16 float4 per e-row
            float q = qs[e];
            float4 a = W0k[i], d = W0d[i], m = W0m[i];
            float4 r;
            r.x = a.x - d.x + q * m.x;
            r.y = a.y - d.y + q * m.y;
            r.z = a.z - d.z + q * m.z;
            r.w = a.w - d.w + q * m.w;
            wf[i] = r;
        }
    }

    // ---- c[h] = b0[h] + sum_e q[e]*(W0q[e][h] + W0d[e][h])  (warps 0-1) ----
    if (tid < H_DIM) {
        float acc = b0[tid];
        #pragma unroll 8
        for (int e = 0; e < E_DIM; e++) {
            acc += qs[e] * (W0[e * H_DIM + tid] + W0[(256 + e) * H_DIM + tid]);
        }
        cs[tid] = acc;
    }

    // ---- transpose-load keys into ks[e][t] (zero-pad t >= T) ----
    {
        const int t = tid;                 // 0..255, warp-contiguous
        const bool valid = t < T_DIM;
        const float4* krow = (const float4*)(keys + ((long)b * T_DIM + (valid ? t : 0)) * E_DIM);
        #pragma unroll
        for (int e0 = 0; e0 < E_DIM; e0 += 4) {
            float4 v = valid ? krow[e0 >> 2] : make_float4(0.f, 0.f, 0.f, 0.f);
            ks[(e0 + 0) * T_TILE + t] = v.x;
            ks[(e0 + 1) * T_TILE + t] = v.y;
            ks[(e0 + 2) * T_TILE + t] = v.z;
            ks[(e0 + 3) * T_TILE + t] = v.w;
        }
    }
    __syncthreads();

    // ---- main GEMM: h_pre[t][h] = c[h] + sum_e ks[e][t]*Weff[e][h] ----
    const int tc = tid & 7;    // h-group 0..7
    const int tr = tid >> 3;   // t-group 0..31
    const int h0 = tc * 8;
    const int t0 = tr * 8;

    // acc[i][j]: rows t0+i, packed h pair (h0+2j, h0+2j+1); init with c
    unsigned long long acc[8][4];
    {
        const unsigned long long* cp = (const unsigned long long*)(cs + h0);
        unsigned long long c0 = cp[0], c1 = cp[1], c2 = cp[2], c3 = cp[3];
        #pragma unroll
        for (int i = 0; i < 8; i++) {
            acc[i][0] = c0; acc[i][1] = c1; acc[i][2] = c2; acc[i][3] = c3;
        }
    }

    #pragma unroll 4
    for (int e = 0; e < E_DIM; e++) {
        // b-operand: Weff[e][h0..h0+7] as 4 packed f32x2 (2x LDS.128)
        const ulonglong2* bp = (const ulonglong2*)(weff + e * H_DIM + h0);
        ulonglong2 bA = bp[0], bB = bp[1];
        // a-operand: ks[e][t0..t0+7] (2x LDS.128)
        const float4* ap = (const float4*)(ks + e * T_TILE + t0);
        float4 a0 = ap[0], a1 = ap[1];
        float av[8] = {a0.x, a0.y, a0.z, a0.w, a1.x, a1.y, a1.z, a1.w};
        #pragma unroll
        for (int i = 0; i < 8; i++) {
            unsigned long long apk;
            asm("mov.b64 %0, {%1, %1};" : "=l"(apk) : "f"(av[i]));
            FMA2(acc[i][0], apk, bA.x);
            FMA2(acc[i][1], apk, bA.y);
            FMA2(acc[i][2], apk, bB.x);
            FMA2(acc[i][3], apk, bB.y);
        }
    }

    // ---- epilogue: relu, dot with W1, reduce over 8 h-groups, store ----
    float w1r[8];
    #pragma unroll
    for (int j = 0; j < 8; j++) w1r[j] = w1s[h0 + j];
    const float bias1 = b1[0];

    #pragma unroll
    for (int i = 0; i < 8; i++) {
        float s = 0.f;
        #pragma unroll
        for (int j = 0; j < 4; j++) {
            float lo, hi;
            asm("mov.b64 {%0, %1}, %2;" : "=f"(lo), "=f"(hi) : "l"(acc[i][j]));
            s += fmaxf(lo, 0.f) * w1r[2 * j] + fmaxf(hi, 0.f) * w1r[2 * j + 1];
        }
        // reduce across the 8 h-threadcols (contiguous 8-lane groups in warp)
        s += __shfl_xor_sync(0xffffffffu, s, 1);
        s += __shfl_xor_sync(0xffffffffu, s, 2);
        s += __shfl_xor_sync(0xffffffffu, s, 4);
        const int t = t0 + i;
        if (tc == 0 && t < T_DIM) out[b * T_DIM + t] = s + bias1;
    }
}

extern "C" void kernel_launch(void* const* d_in, const int* in_sizes, int n_in,
                              void* d_out, int out_size)
{
    const float* query = (const float*)d_in[0];
    const float* keys  = (const float*)d_in[1];
    const float* W0    = (const float*)d_in[2];
    const float* b0    = (const float*)d_in[3];
    const float* W1    = (const float*)d_in[4];
    const float* b1    = (const float*)d_in[5];
    float* out = (float*)d_out;

    cudaFuncSetAttribute(lau_kernel, cudaFuncAttributeMaxDynamicSharedMemorySize, SMEM_BYTES);
    lau_kernel<<<B_DIM, 256, SMEM_BYTES>>>(query, keys, W0, b0, W1, b1, out);
}